// round 11
// baseline (speedup 1.0000x reference)
#include <cuda_runtime.h>
#include <cuda_fp16.h>
#include <math.h>
#include <stdint.h>

#define BB 4
#define NN 4096
#define DD 64
#define SHIFT 64.0f
#define L2E 1.4426950408889634f
#define LN2 0.6931471805599453f
#define TWO_L2E (2.0f * L2E)
#define TWOGL2E (80000.0f * L2E)      /* 2*gamma*log2(e) */
#define PDTH (-0.00113f)              /* -STH/2 : acc = -d^2/2 threshold */

#define ROWS 32                       /* rows per CTA */
#define T_TILES 32
#define THREADS 128
#define NCTA (BB * NN / ROWS)         /* 512 */

/* ---- ce smem layout (bytes) ---- */
#define OFF_A    0                    /* 4096 */
#define OFF_B    4096                 /* 2 x 16384 */
#define OFF_COLC 36864                /* 2 x 2048 */
#define OFF_RED  40960                /* 3*32 floats = 384 */
#define OFF_WSUM 41344                /* 16 floats */
#define SMEM_CE  41472

/* ---- device scratch ---- */
__device__ __align__(16) unsigned char g_f1h[BB * NN * 128];
__device__ __align__(16) unsigned char g_f2h[BB * NN * 128];
/* per 128-col tile, 512 floats: [0:128) kv  [128:256) pdk=-|p^|^2/2  [256:512) pdh fp16 xyz0 */
__device__ float g_colc[BB * T_TILES * 512];
__device__ float g_rowk[BB * NN];     /* L2E*(SHIFT - n1) */
__device__ float g_cep[BB * 128];
__device__ float g_regp[64];
__device__ unsigned int g_ctr = 0;

/* ------------------------------- asm helpers ----------------------------- */
__device__ __forceinline__ uint32_t smem_u32(const void* p) {
    uint32_t a;
    asm("{ .reg .u64 t; cvta.to.shared.u64 t, %1; cvt.u32.u64 %0, t; }" : "=r"(a) : "l"(p));
    return a;
}
__device__ __forceinline__ float ex2_(float x) {
    float r;
    asm("ex2.approx.ftz.f32 %0, %1;" : "=f"(r) : "f"(x));
    return r;
}
#define CPA16(dst, src) \
    asm volatile("cp.async.cg.shared.global [%0], [%1], 16;" :: "r"(dst), "l"(src))
#define CPA_COMMIT() asm volatile("cp.async.commit_group;" ::: "memory")
#define CPA_WAIT0()  asm volatile("cp.async.wait_group 0;" ::: "memory")

#define LDSM4(r, addr) \
    asm volatile("ldmatrix.sync.aligned.m8n8.x4.shared.b16 {%0,%1,%2,%3}, [%4];" \
        : "=r"((r)[0]), "=r"((r)[1]), "=r"((r)[2]), "=r"((r)[3]) : "r"(addr))

#define MMA16816(c, a, b0_, b1_) \
    asm volatile("mma.sync.aligned.m16n8k16.row.col.f32.f16.f16.f32 " \
        "{%0,%1,%2,%3},{%4,%5,%6,%7},{%8,%9},{%0,%1,%2,%3};" \
        : "+f"((c)[0]), "+f"((c)[1]), "+f"((c)[2]), "+f"((c)[3]) \
        : "r"((a)[0]), "r"((a)[1]), "r"((a)[2]), "r"((a)[3]), "r"(b0_), "r"(b1_))

#define MMA1688(c, a0_, a1_, b_) \
    asm volatile("mma.sync.aligned.m16n8k8.row.col.f32.f16.f16.f32 " \
        "{%0,%1,%2,%3},{%4,%5},{%6},{%0,%1,%2,%3};" \
        : "+f"((c)[0]), "+f"((c)[1]), "+f"((c)[2]), "+f"((c)[3]) \
        : "r"(a0_), "r"(a1_), "r"(b_))

/* ------------------------------- prep kernel ----------------------------- */
__device__ __forceinline__ uint4 cvt8h(const float* f) {
    uint32_t h[4];
#pragma unroll
    for (int i = 0; i < 4; i++) {
        __half2 hh = __floats2half2_rn(f[2 * i], f[2 * i + 1]);
        h[i] = *reinterpret_cast<uint32_t*>(&hh);
    }
    return make_uint4(h[0], h[1], h[2], h[3]);
}

__global__ void __launch_bounds__(256)
prep_kernel(const float* __restrict__ points,
            const float* __restrict__ f1,
            const float* __restrict__ f2)
{
    __shared__ float wsum[8];
    const int tid = threadIdx.x;
    const int row = blockIdx.x * 256 + tid;
    const int b = row >> 12, n = row & (NN - 1);
    const int t = n >> 7, rin = n & 127;
    const size_t tb = ((size_t)(b * T_TILES + t)) * 16384 + (size_t)rin * 128;
    const int sw = rin & 7;

    float f[DD];
    float n1 = 0.f, n2 = 0.f;
    {
        const float4* v = (const float4*)(f1 + (size_t)row * DD);
#pragma unroll
        for (int j = 0; j < DD / 4; j++) {
            float4 x = v[j];
            f[4 * j] = x.x; f[4 * j + 1] = x.y; f[4 * j + 2] = x.z; f[4 * j + 3] = x.w;
            n1 = fmaf(x.x, x.x, n1); n1 = fmaf(x.y, x.y, n1);
            n1 = fmaf(x.z, x.z, n1); n1 = fmaf(x.w, x.w, n1);
        }
#pragma unroll
        for (int c = 0; c < 8; c++)
            *reinterpret_cast<uint4*>(g_f1h + tb + (size_t)(((c ^ sw) << 4))) = cvt8h(f + 8 * c);
    }
    {
        const float4* v = (const float4*)(f2 + (size_t)row * DD);
#pragma unroll
        for (int j = 0; j < DD / 4; j++) {
            float4 x = v[j];
            f[4 * j] = x.x; f[4 * j + 1] = x.y; f[4 * j + 2] = x.z; f[4 * j + 3] = x.w;
            n2 = fmaf(x.x, x.x, n2); n2 = fmaf(x.y, x.y, n2);
            n2 = fmaf(x.z, x.z, n2); n2 = fmaf(x.w, x.w, n2);
        }
#pragma unroll
        for (int c = 0; c < 8; c++)
            *reinterpret_cast<uint4*>(g_f2h + tb + (size_t)(((c ^ sw) << 4))) = cvt8h(f + 8 * c);
    }
    g_rowk[row] = L2E * (SHIFT - n1);

    /* fp16-rounded coords + norm FROM the rounded values (diag stays 0) */
    const float px = points[(size_t)row * 3 + 0];
    const float py = points[(size_t)row * 3 + 1];
    const float pz = points[(size_t)row * 3 + 2];
    __half2 hxy = __floats2half2_rn(px, py);
    __half2 hz0 = __floats2half2_rn(pz, 0.f);
    const float xf = __half2float(__low2half(hxy));
    const float yf = __half2float(__high2half(hxy));
    const float zf = __half2float(__low2half(hz0));
    const float np = fmaf(xf, xf, fmaf(yf, yf, zf * zf));

    const int cb = (b * T_TILES + t) * 512;
    g_colc[cb + rin]       = -L2E * n2;            /* kv */
    g_colc[cb + 128 + rin] = -0.5f * np;           /* pdk */
    uint2 wp;
    wp.x = *reinterpret_cast<uint32_t*>(&hxy);
    wp.y = *reinterpret_cast<uint32_t*>(&hz0);
    reinterpret_cast<uint2*>(g_colc + cb + 256)[rin] = wp;

    /* reg loss partial */
    float s = n1 + n2;
#pragma unroll
    for (int o = 16; o > 0; o >>= 1) s += __shfl_down_sync(0xffffffffu, s, o);
    if ((tid & 31) == 0) wsum[tid >> 5] = s;
    __syncthreads();
    if (tid < 8) {
        float v = wsum[tid];
        v += __shfl_down_sync(0xffu, v, 4);
        v += __shfl_down_sync(0xffu, v, 2);
        v += __shfl_down_sync(0xffu, v, 1);
        if (tid == 0) g_regp[blockIdx.x] = v;
    }
}

/* -------------------------------- ce kernel ------------------------------ */
__global__ void __launch_bounds__(THREADS, 5)
ce_kernel(const float* __restrict__ w, float* __restrict__ out)
{
    extern __shared__ char sm[];
    const uint32_t smb = smem_u32(sm);
    const int tid = threadIdx.x;
    const int wid = tid >> 5, lane = tid & 31;
    const int rg = wid & 1;          /* row group (16 rows), 2 groups = 32 rows */
    const int ch = wid >> 1;         /* column half (64 cols) */
    const int b = blockIdx.y, bx = blockIdx.x;     /* bx: 0..127 */

    /* prologue: A slice (32 rows) + B tile 0 + colc 0 */
    {
        const size_t abase = ((size_t)(b * T_TILES + (bx >> 2))) * 16384
                           + (size_t)(bx & 3) * 32 * 128;
        const size_t bbase = ((size_t)(b * T_TILES + 0)) * 16384;
#pragma unroll
        for (int j = 0; j < 2; j++) {
            const uint32_t c16 = (uint32_t)(tid + j * 128) * 16;
            CPA16(smb + OFF_A + c16, g_f1h + abase + c16);
        }
#pragma unroll
        for (int j = 0; j < 8; j++) {
            const uint32_t c16 = (uint32_t)(tid + j * 128) * 16;
            CPA16(smb + OFF_B + c16, g_f2h + bbase + c16);
        }
        {
            const uint32_t c16 = (uint32_t)tid * 16;
            CPA16(smb + OFF_COLC + c16,
                  (const char*)(g_colc + (size_t)(b * T_TILES) * 512) + c16);
        }
        CPA_COMMIT();
    }

    const int q = lane & 3;
    const int kq = lane >> 2;
    const int r0 = rg * 16 + kq;                   /* 0..15 or 16..31 */
    const int n0 = bx * ROWS + r0;
    const float rowka = g_rowk[b * NN + n0];
    const float rowkb = g_rowk[b * NN + n0 + 8];

    /* pd row constants + A fragment (fp16 coords of this CTA's rows) */
    const float* mycol = g_colc + (size_t)(b * T_TILES + (bx >> 2)) * 512;
    const int rowoff = (bx & 3) * 32;
    const float prow2a = mycol[128 + rowoff + r0];
    const float prow2b = mycol[128 + rowoff + r0 + 8];
    const uint2* pdh_my = reinterpret_cast<const uint2*>(mycol + 256) + rowoff;
    const int sel = lane & 3;
    uint32_t apd0, apd1;
    {
        uint2 wa0 = pdh_my[r0];
        uint2 wa1 = pdh_my[r0 + 8];
        apd0 = (sel == 0) ? wa0.x : ((sel == 1) ? wa0.y : 0u);
        apd1 = (sel == 0) ? wa1.x : ((sel == 1) ? wa1.y : 0u);
    }

    CPA_WAIT0();
    __syncthreads();

    /* persistent feature A fragments (16 rows x 64 k) */
    const int g = lane >> 3, li = lane & 7, gh = g >> 1;
    uint32_t af[4][4];
    {
        const int rA = rg * 16 + (g & 1) * 8 + li;
        const uint32_t ab = smb + OFF_A + rA * 128;
        const int sA = rA & 7;
#pragma unroll
        for (int kc = 0; kc < 4; kc++)
            LDSM4(af[kc], ab + (uint32_t)(((2 * kc + gh) ^ sA) << 4));
    }
    const int rl = (g & 1) * 8 + li;
    const int sB = rl & 7;

    float zpd0 = 0.f, tz0 = 0.f, zfd0 = 0.f;
    float zpd1 = 0.f, tz1 = 0.f, zfd1 = 0.f;

    for (int t = 0; t < T_TILES; t++) {
        const int bf = t & 1;
        if (t + 1 < T_TILES) {
            const int nbf = bf ^ 1;
            const size_t bbase = ((size_t)(b * T_TILES + t + 1)) * 16384;
            const uint32_t dstB = smb + OFF_B + nbf * 16384;
#pragma unroll
            for (int j = 0; j < 8; j++) {
                const uint32_t c16 = (uint32_t)(tid + j * 128) * 16;
                CPA16(dstB + c16, g_f2h + bbase + c16);
            }
            {
                const uint32_t c16 = (uint32_t)tid * 16;
                CPA16(smb + OFF_COLC + nbf * 2048 + c16,
                      (const char*)(g_colc + (size_t)(b * T_TILES + t + 1) * 512) + c16);
            }
            CPA_COMMIT();
        }

        const float* colcp = (const float*)(sm + OFF_COLC + bf * 2048);
        const float* pdkp = colcp + 128;
        const uint2* pdhp = reinterpret_cast<const uint2*>(colcp + 256);
        const uint32_t bbuf = smb + OFF_B + bf * 16384;

#pragma unroll
        for (int cpl = 0; cpl < 4; cpl++) {
            const int cpg = ch * 4 + cpl;          /* 16-col group index */
            uint32_t bfrag[4][4];
            const uint32_t bb = bbuf + cpg * 2048 + rl * 128;
#pragma unroll
            for (int kc = 0; kc < 4; kc++)
                LDSM4(bfrag[kc], bb + (uint32_t)(((2 * kc + gh) ^ sB) << 4));

            float accA[4] = {0.f, 0.f, 0.f, 0.f};
            float accB[4] = {0.f, 0.f, 0.f, 0.f};
#pragma unroll
            for (int kc = 0; kc < 4; kc++) {
                MMA16816(accA, af[kc], bfrag[kc][0], bfrag[kc][2]);
                MMA16816(accB, af[kc], bfrag[kc][1], bfrag[kc][3]);
            }

            const int lc0 = cpg * 16 + 2 * q;
            const int lc1 = lc0 + 8;

            /* ---- pd MMAs (K=8, coords) ---- */
            uint32_t bpd0, bpd1;
            {
                const int cb0 = cpg * 16 + kq;
                uint2 wb0 = pdhp[cb0];
                uint2 wb1 = pdhp[cb0 + 8];
                bpd0 = (sel == 0) ? wb0.x : ((sel == 1) ? wb0.y : 0u);
                bpd1 = (sel == 0) ? wb1.x : ((sel == 1) ? wb1.y : 0u);
            }
            const float2 pk0 = *(const float2*)(pdkp + lc0);
            const float2 pk1 = *(const float2*)(pdkp + lc1);
            float accP0[4] = { prow2a + pk0.x, prow2a + pk0.y,
                               prow2b + pk0.x, prow2b + pk0.y };
            float accP1[4] = { prow2a + pk1.x, prow2a + pk1.y,
                               prow2b + pk1.x, prow2b + pk1.y };
            MMA1688(accP0, apd0, apd1, bpd0);
            MMA1688(accP1, apd0, apd1, bpd1);

            /* ---- feature side ---- */
            const float2 k0 = *(const float2*)(colcp + lc0);
            const float2 k1 = *(const float2*)(colcp + lc1);
            const float za0 = fmaf(accA[0], TWO_L2E, rowka + k0.x);
            const float za1 = fmaf(accA[1], TWO_L2E, rowka + k0.y);
            const float za2 = fmaf(accB[0], TWO_L2E, rowka + k1.x);
            const float za3 = fmaf(accB[1], TWO_L2E, rowka + k1.y);
            const float zb0 = fmaf(accA[2], TWO_L2E, rowkb + k0.x);
            const float zb1 = fmaf(accA[3], TWO_L2E, rowkb + k0.y);
            const float zb2 = fmaf(accB[2], TWO_L2E, rowkb + k1.x);
            const float zb3 = fmaf(accB[3], TWO_L2E, rowkb + k1.y);
            zfd0 += ex2_(za0) + ex2_(za1) + ex2_(za2) + ex2_(za3);
            zfd1 += ex2_(zb0) + ex2_(zb1) + ex2_(zb2) + ex2_(zb3);

            /* ---- pd near-pair path (acc = -d^2/2) ---- */
            {
                const float ma = fmaxf(fmaxf(accP0[0], accP0[1]),
                                       fmaxf(accP1[0], accP1[1]));
                if (ma > PDTH) {
                    float e;
                    e = ex2_(accP0[0] * TWOGL2E); zpd0 += e; tz0 = fmaf(e, za0, tz0);
                    e = ex2_(accP0[1] * TWOGL2E); zpd0 += e; tz0 = fmaf(e, za1, tz0);
                    e = ex2_(accP1[0] * TWOGL2E); zpd0 += e; tz0 = fmaf(e, za2, tz0);
                    e = ex2_(accP1[1] * TWOGL2E); zpd0 += e; tz0 = fmaf(e, za3, tz0);
                }
            }
            {
                const float mb = fmaxf(fmaxf(accP0[2], accP0[3]),
                                       fmaxf(accP1[2], accP1[3]));
                if (mb > PDTH) {
                    float e;
                    e = ex2_(accP0[2] * TWOGL2E); zpd1 += e; tz1 = fmaf(e, zb0, tz1);
                    e = ex2_(accP0[3] * TWOGL2E); zpd1 += e; tz1 = fmaf(e, zb1, tz1);
                    e = ex2_(accP1[2] * TWOGL2E); zpd1 += e; tz1 = fmaf(e, zb2, tz1);
                    e = ex2_(accP1[3] * TWOGL2E); zpd1 += e; tz1 = fmaf(e, zb3, tz1);
                }
            }
        }

        if (t + 1 < T_TILES) CPA_WAIT0();
        __syncthreads();
    }

    /* reduce quad lanes */
#pragma unroll
    for (int o = 1; o <= 2; o <<= 1) {
        zfd0 += __shfl_xor_sync(0xffffffffu, zfd0, o);
        zpd0 += __shfl_xor_sync(0xffffffffu, zpd0, o);
        tz0  += __shfl_xor_sync(0xffffffffu, tz0, o);
        zfd1 += __shfl_xor_sync(0xffffffffu, zfd1, o);
        zpd1 += __shfl_xor_sync(0xffffffffu, zpd1, o);
        tz1  += __shfl_xor_sync(0xffffffffu, tz1, o);
    }
    /* combine the two column halves via smem */
    float* red = (float*)(sm + OFF_RED);
    if (ch == 1 && q == 0) {
        red[r0] = zfd0;          red[r0 + 8] = zfd1;
        red[32 + r0] = zpd0;     red[32 + r0 + 8] = zpd1;
        red[64 + r0] = tz0;      red[64 + r0 + 8] = tz1;
    }
    __syncthreads();
    float val = 0.f;
    if (ch == 0 && q == 0) {
        const float ZF0 = zfd0 + red[r0];
        const float ZF1 = zfd1 + red[r0 + 8];
        const float ZP0 = zpd0 + red[32 + r0];
        const float ZP1 = zpd1 + red[32 + r0 + 8];
        const float TZ0 = tz0 + red[64 + r0];
        const float TZ1 = tz1 + red[64 + r0 + 8];
        const float TP0 = fmaf(TZ0, LN2, -SHIFT * ZP0);
        const float TP1 = fmaf(TZ1, LN2, -SHIFT * ZP1);
        const int na = b * NN + n0, nb_ = na + 8;
        const float ce0 = (logf(ZF0) - SHIFT) - TP0 / ZP0;
        const float ce1 = (logf(ZF1) - SHIFT) - TP1 / ZP1;
        val = w[na] * ce0 + w[nb_] * ce1;
    }
#pragma unroll
    for (int o = 16; o >= 4; o >>= 1) val += __shfl_down_sync(0xffffffffu, val, o);
    float* wsum = (float*)(sm + OFF_WSUM);
    if (lane == 0) wsum[wid] = val;
    __syncthreads();
    if (tid == 0) g_cep[b * 128 + bx] = wsum[0] + wsum[1];   /* ch==0 warps 0,1 */

    /* ---- ticket: last CTA writes all 8 outputs ---- */
    __shared__ unsigned int lastTicket;
    __threadfence();
    if (tid == 0) lastTicket = atomicAdd(&g_ctr, 1u);
    __syncthreads();
    if (lastTicket == NCTA - 1) {
        __threadfence();
        const int bb2 = tid >> 5, ln = tid & 31;
        float v = 0.f;
#pragma unroll
        for (int j = 0; j < 4; j++) v += g_cep[bb2 * 128 + ln + 32 * j];
#pragma unroll
        for (int o = 16; o > 0; o >>= 1) v += __shfl_down_sync(0xffffffffu, v, o);
        if (ln == 0) out[bb2] = v;
        if (tid < 64) {
            float r = g_regp[tid];
#pragma unroll
            for (int o = 8; o > 0; o >>= 1) r += __shfl_down_sync(0xffffffffu, r, o, 16);
            if ((tid & 15) == 0) out[4 + (tid >> 4)] = r * (1.0f / (float)(NN * DD));
        }
        if (tid == 0) g_ctr = 0;
    }
}

/* -------------------------------- launcher ------------------------------- */
extern "C" void kernel_launch(void* const* d_in, const int* in_sizes, int n_in,
                              void* d_out, int out_size)
{
    const float* points = (const float*)d_in[0];
    const float* f1     = (const float*)d_in[1];
    const float* f2     = (const float*)d_in[2];
    const float* w      = (const float*)d_in[3];
    float* out          = (float*)d_out;

    static bool attr_set = false;
    if (!attr_set) {
        cudaFuncSetAttribute(ce_kernel, cudaFuncAttributeMaxDynamicSharedMemorySize, SMEM_CE);
        attr_set = true;
    }

    prep_kernel<<<BB * NN / 256, 256>>>(points, f1, f2);
    ce_kernel<<<dim3(NN / ROWS, BB), THREADS, SMEM_CE>>>(w, out);
}

// round 12
// speedup vs baseline: 1.1930x; 1.1930x over previous
#include <cuda_runtime.h>
#include <cuda_fp16.h>
#include <math.h>
#include <stdint.h>

#define BB 4
#define NN 4096
#define DD 64
#define L2E 1.4426950408889634f
#define LN2 0.6931471805599453f
#define TWO_L2E (2.0f * L2E)
#define TWOGL2E (80000.0f * L2E)      /* 2*gamma*log2(e) */
#define PDTH (-0.00113f)              /* -STH/2 : acc = -d^2/2 threshold */

#define ROWS 64                       /* rows per CTA */
#define T_TILES 32
#define THREADS 256
#define NCTA (BB * NN / ROWS)         /* 256 */

/* ---- ce smem layout (bytes) ---- */
#define OFF_A    0                    /* 8192 */
#define OFF_B    8192                 /* 2 x 16384 */
#define OFF_COLC 40960                /* 2 x 3072 */
#define OFF_RED  47104                /* 3*64 floats = 768 */
#define OFF_WSUM 47872                /* 16 floats */
#define SMEM_CE  47936

/* ---- device scratch ---- */
__device__ __align__(16) unsigned char g_f1h[BB * NN * 128];
__device__ __align__(16) unsigned char g_f2h[BB * NN * 128];
/* per 128-col tile, 768 floats:
   [0:128) kv=-L2E*n2  [128:256) pdk=-|p^|^2/2  [256:768) u32 tbl[c][4]={xy,z0,0,0} */
__device__ float g_colc[BB * T_TILES * 768];
__device__ float g_cep[BB * 64];
__device__ float g_regp[64];
__device__ unsigned int g_ctr = 0;

/* ------------------------------- asm helpers ----------------------------- */
__device__ __forceinline__ uint32_t smem_u32(const void* p) {
    uint32_t a;
    asm("{ .reg .u64 t; cvta.to.shared.u64 t, %1; cvt.u32.u64 %0, t; }" : "=r"(a) : "l"(p));
    return a;
}
__device__ __forceinline__ float ex2_(float x) {
    float r;
    asm("ex2.approx.ftz.f32 %0, %1;" : "=f"(r) : "f"(x));
    return r;
}
#define CPA16(dst, src) \
    asm volatile("cp.async.cg.shared.global [%0], [%1], 16;" :: "r"(dst), "l"(src))
#define CPA_COMMIT() asm volatile("cp.async.commit_group;" ::: "memory")
#define CPA_WAIT0()  asm volatile("cp.async.wait_group 0;" ::: "memory")

#define LDSM4(r, addr) \
    asm volatile("ldmatrix.sync.aligned.m8n8.x4.shared.b16 {%0,%1,%2,%3}, [%4];" \
        : "=r"((r)[0]), "=r"((r)[1]), "=r"((r)[2]), "=r"((r)[3]) : "r"(addr))

#define MMA16816(c, a, b0_, b1_) \
    asm volatile("mma.sync.aligned.m16n8k16.row.col.f32.f16.f16.f32 " \
        "{%0,%1,%2,%3},{%4,%5,%6,%7},{%8,%9},{%0,%1,%2,%3};" \
        : "+f"((c)[0]), "+f"((c)[1]), "+f"((c)[2]), "+f"((c)[3]) \
        : "r"((a)[0]), "r"((a)[1]), "r"((a)[2]), "r"((a)[3]), "r"(b0_), "r"(b1_))

#define MMA1688(c, a0_, a1_, b_) \
    asm volatile("mma.sync.aligned.m16n8k8.row.col.f32.f16.f16.f32 " \
        "{%0,%1,%2,%3},{%4,%5},{%6},{%0,%1,%2,%3};" \
        : "+f"((c)[0]), "+f"((c)[1]), "+f"((c)[2]), "+f"((c)[3]) \
        : "r"(a0_), "r"(a1_), "r"(b_))

/* ------------------------------- prep kernel ----------------------------- */
__device__ __forceinline__ uint4 cvt8h(const float* f) {
    uint32_t h[4];
#pragma unroll
    for (int i = 0; i < 4; i++) {
        __half2 hh = __floats2half2_rn(f[2 * i], f[2 * i + 1]);
        h[i] = *reinterpret_cast<uint32_t*>(&hh);
    }
    return make_uint4(h[0], h[1], h[2], h[3]);
}

__global__ void __launch_bounds__(256)
prep_kernel(const float* __restrict__ points,
            const float* __restrict__ f1,
            const float* __restrict__ f2)
{
    __shared__ float wsum[8];
    const int tid = threadIdx.x;
    const int row = blockIdx.x * 256 + tid;
    const int b = row >> 12, n = row & (NN - 1);
    const int t = n >> 7, rin = n & 127;
    const size_t tb = ((size_t)(b * T_TILES + t)) * 16384 + (size_t)rin * 128;
    const int sw = rin & 7;

    float f[DD];
    float n1 = 0.f, n2 = 0.f;
    {
        const float4* v = (const float4*)(f1 + (size_t)row * DD);
#pragma unroll
        for (int j = 0; j < DD / 4; j++) {
            float4 x = v[j];
            f[4 * j] = x.x; f[4 * j + 1] = x.y; f[4 * j + 2] = x.z; f[4 * j + 3] = x.w;
            n1 = fmaf(x.x, x.x, n1); n1 = fmaf(x.y, x.y, n1);
            n1 = fmaf(x.z, x.z, n1); n1 = fmaf(x.w, x.w, n1);
        }
#pragma unroll
        for (int c = 0; c < 8; c++)
            *reinterpret_cast<uint4*>(g_f1h + tb + (size_t)(((c ^ sw) << 4))) = cvt8h(f + 8 * c);
    }
    {
        const float4* v = (const float4*)(f2 + (size_t)row * DD);
#pragma unroll
        for (int j = 0; j < DD / 4; j++) {
            float4 x = v[j];
            f[4 * j] = x.x; f[4 * j + 1] = x.y; f[4 * j + 2] = x.z; f[4 * j + 3] = x.w;
            n2 = fmaf(x.x, x.x, n2); n2 = fmaf(x.y, x.y, n2);
            n2 = fmaf(x.z, x.z, n2); n2 = fmaf(x.w, x.w, n2);
        }
#pragma unroll
        for (int c = 0; c < 8; c++)
            *reinterpret_cast<uint4*>(g_f2h + tb + (size_t)(((c ^ sw) << 4))) = cvt8h(f + 8 * c);
    }

    /* fp16-rounded coords; norm FROM the rounded values (diag stays exactly 0) */
    const float px = points[(size_t)row * 3 + 0];
    const float py = points[(size_t)row * 3 + 1];
    const float pz = points[(size_t)row * 3 + 2];
    __half2 hxy = __floats2half2_rn(px, py);
    __half2 hz0 = __floats2half2_rn(pz, 0.f);
    const float xf = __half2float(__low2half(hxy));
    const float yf = __half2float(__high2half(hxy));
    const float zf = __half2float(__low2half(hz0));
    const float np = fmaf(xf, xf, fmaf(yf, yf, zf * zf));

    const int cb = (b * T_TILES + t) * 768;
    g_colc[cb + rin]       = -L2E * n2;            /* kv */
    g_colc[cb + 128 + rin] = -0.5f * np;           /* pdk */
    uint4 te;
    te.x = *reinterpret_cast<uint32_t*>(&hxy);
    te.y = *reinterpret_cast<uint32_t*>(&hz0);
    te.z = 0u; te.w = 0u;
    reinterpret_cast<uint4*>(g_colc + cb + 256)[rin] = te;

    /* reg loss partial */
    float s = n1 + n2;
#pragma unroll
    for (int o = 16; o > 0; o >>= 1) s += __shfl_down_sync(0xffffffffu, s, o);
    if ((tid & 31) == 0) wsum[tid >> 5] = s;
    __syncthreads();
    if (tid < 8) {
        float v = wsum[tid];
        v += __shfl_down_sync(0xffu, v, 4);
        v += __shfl_down_sync(0xffu, v, 2);
        v += __shfl_down_sync(0xffu, v, 1);
        if (tid == 0) g_regp[blockIdx.x] = v;
    }
}

/* -------------------------------- ce kernel ------------------------------ */
__global__ void __launch_bounds__(THREADS, 2)
ce_kernel(const float* __restrict__ w, float* __restrict__ out)
{
    extern __shared__ char sm[];
    const uint32_t smb = smem_u32(sm);
    const int tid = threadIdx.x;
    const int wid = tid >> 5, lane = tid & 31;
    const int rg = wid & 3;          /* row group (16 rows) */
    const int ch = wid >> 2;         /* column half */
    const int b = blockIdx.y, bx = blockIdx.x;

    /* prologue: A slice (64 rows) + B tile 0 + colc 0 */
    {
        const size_t abase = ((size_t)(b * T_TILES + (bx >> 1))) * 16384
                           + (size_t)(bx & 1) * 64 * 128;
        const size_t bbase = ((size_t)(b * T_TILES + 0)) * 16384;
#pragma unroll
        for (int j = 0; j < 2; j++) {
            const uint32_t c16 = (uint32_t)(tid + j * 256) * 16;
            CPA16(smb + OFF_A + c16, g_f1h + abase + c16);
        }
#pragma unroll
        for (int j = 0; j < 4; j++) {
            const uint32_t c16 = (uint32_t)(tid + j * 256) * 16;
            CPA16(smb + OFF_B + c16, g_f2h + bbase + c16);
        }
        if (tid < 192) {
            const uint32_t c16 = (uint32_t)tid * 16;
            CPA16(smb + OFF_COLC + c16,
                  (const char*)(g_colc + (size_t)(b * T_TILES) * 768) + c16);
        }
        CPA_COMMIT();
    }

    const int q = lane & 3;
    const int kq = lane >> 2;
    const int r0 = rg * 16 + kq;
    const int n0 = bx * ROWS + r0;

    /* pd row constants + fragments (from this CTA's column tile in gmem) */
    const float* mycol = g_colc + (size_t)(b * T_TILES + (bx >> 1)) * 768;
    const int rowoff = (bx & 1) * 64;
    const float prow2a = mycol[128 + rowoff + r0];
    const float prow2b = mycol[128 + rowoff + r0 + 8];
    const uint32_t* rowtbl = reinterpret_cast<const uint32_t*>(mycol + 256);
    const int sel = lane & 3;
    const uint32_t apd0 = rowtbl[(rowoff + r0) * 4 + sel];
    const uint32_t apd1 = rowtbl[(rowoff + r0 + 8) * 4 + sel];

    CPA_WAIT0();
    __syncthreads();

    /* persistent feature A fragments (16 rows x 64 k) */
    const int g = lane >> 3, li = lane & 7, gh = g >> 1;
    uint32_t af[4][4];
    {
        const int rA = rg * 16 + (g & 1) * 8 + li;
        const uint32_t ab = smb + OFF_A + rA * 128;
        const int sA = rA & 7;
#pragma unroll
        for (int kc = 0; kc < 4; kc++)
            LDSM4(af[kc], ab + (uint32_t)(((2 * kc + gh) ^ sA) << 4));
    }
    const int rl = (g & 1) * 8 + li;
    const int sB = rl & 7;

    float zpd0 = 0.f, tz0 = 0.f, zfd0 = 0.f;
    float zpd1 = 0.f, tz1 = 0.f, zfd1 = 0.f;

    for (int t = 0; t < T_TILES; t++) {
        const int bf = t & 1;
        if (t + 1 < T_TILES) {
            const int nbf = bf ^ 1;
            const size_t bbase = ((size_t)(b * T_TILES + t + 1)) * 16384;
            const uint32_t dstB = smb + OFF_B + nbf * 16384;
#pragma unroll
            for (int j = 0; j < 4; j++) {
                const uint32_t c16 = (uint32_t)(tid + j * 256) * 16;
                CPA16(dstB + c16, g_f2h + bbase + c16);
            }
            if (tid < 192) {
                const uint32_t c16 = (uint32_t)tid * 16;
                CPA16(smb + OFF_COLC + nbf * 3072 + c16,
                      (const char*)(g_colc + (size_t)(b * T_TILES + t + 1) * 768) + c16);
            }
            CPA_COMMIT();
        }

        const float* colcp = (const float*)(sm + OFF_COLC + bf * 3072);
        const float* pdkp = colcp + 128;
        const uint32_t* ptbl = reinterpret_cast<const uint32_t*>(colcp + 256);
        const uint32_t bbuf = smb + OFF_B + bf * 16384;

#pragma unroll
        for (int cpl = 0; cpl < 4; cpl++) {
            const int cpg = ch * 4 + cpl;          /* 16-col group index */
            uint32_t bfrag[4][4];
            const uint32_t bb = bbuf + cpg * 2048 + rl * 128;
#pragma unroll
            for (int kc = 0; kc < 4; kc++)
                LDSM4(bfrag[kc], bb + (uint32_t)(((2 * kc + gh) ^ sB) << 4));

            /* split chains: depth 2 instead of 4 */
            float accA[4] = {0.f, 0.f, 0.f, 0.f};
            float accB[4] = {0.f, 0.f, 0.f, 0.f};
            float accC[4] = {0.f, 0.f, 0.f, 0.f};
            float accD[4] = {0.f, 0.f, 0.f, 0.f};
#pragma unroll
            for (int kc = 0; kc < 2; kc++) {
                MMA16816(accA, af[kc], bfrag[kc][0], bfrag[kc][2]);
                MMA16816(accB, af[kc], bfrag[kc][1], bfrag[kc][3]);
                MMA16816(accC, af[kc + 2], bfrag[kc + 2][0], bfrag[kc + 2][2]);
                MMA16816(accD, af[kc + 2], bfrag[kc + 2][1], bfrag[kc + 2][3]);
            }
#pragma unroll
            for (int i = 0; i < 4; i++) { accA[i] += accC[i]; accB[i] += accD[i]; }

            const int lc0 = cpg * 16 + 2 * q;
            const int lc1 = lc0 + 8;

            /* ---- pd MMAs (K=8, coords) ---- */
            const uint32_t bpd0 = ptbl[(cpg * 16 + kq) * 4 + sel];
            const uint32_t bpd1 = ptbl[(cpg * 16 + kq + 8) * 4 + sel];
            const float2 pk0 = *(const float2*)(pdkp + lc0);
            const float2 pk1 = *(const float2*)(pdkp + lc1);
            float accP0[4] = { prow2a + pk0.x, prow2a + pk0.y,
                               prow2b + pk0.x, prow2b + pk0.y };
            float accP1[4] = { prow2a + pk1.x, prow2a + pk1.y,
                               prow2b + pk1.x, prow2b + pk1.y };
            MMA1688(accP0, apd0, apd1, bpd0);
            MMA1688(accP1, apd0, apd1, bpd1);

            /* ---- feature side: za = L2E*(2dot - n2); n1 cancels in ce ---- */
            const float2 k0 = *(const float2*)(colcp + lc0);
            const float2 k1 = *(const float2*)(colcp + lc1);
            const float za0 = fmaf(accA[0], TWO_L2E, k0.x);
            const float za1 = fmaf(accA[1], TWO_L2E, k0.y);
            const float za2 = fmaf(accB[0], TWO_L2E, k1.x);
            const float za3 = fmaf(accB[1], TWO_L2E, k1.y);
            const float zb0 = fmaf(accA[2], TWO_L2E, k0.x);
            const float zb1 = fmaf(accA[3], TWO_L2E, k0.y);
            const float zb2 = fmaf(accB[2], TWO_L2E, k1.x);
            const float zb3 = fmaf(accB[3], TWO_L2E, k1.y);
            zfd0 += ex2_(za0) + ex2_(za1) + ex2_(za2) + ex2_(za3);
            zfd1 += ex2_(zb0) + ex2_(zb1) + ex2_(zb2) + ex2_(zb3);

            /* ---- pd near-pair path (acc = -d^2/2) ---- */
            {
                const float ma = fmaxf(fmaxf(accP0[0], accP0[1]),
                                       fmaxf(accP1[0], accP1[1]));
                if (ma > PDTH) {
                    float e;
                    e = ex2_(accP0[0] * TWOGL2E); zpd0 += e; tz0 = fmaf(e, za0, tz0);
                    e = ex2_(accP0[1] * TWOGL2E); zpd0 += e; tz0 = fmaf(e, za1, tz0);
                    e = ex2_(accP1[0] * TWOGL2E); zpd0 += e; tz0 = fmaf(e, za2, tz0);
                    e = ex2_(accP1[1] * TWOGL2E); zpd0 += e; tz0 = fmaf(e, za3, tz0);
                }
            }
            {
                const float mb = fmaxf(fmaxf(accP0[2], accP0[3]),
                                       fmaxf(accP1[2], accP1[3]));
                if (mb > PDTH) {
                    float e;
                    e = ex2_(accP0[2] * TWOGL2E); zpd1 += e; tz1 = fmaf(e, zb0, tz1);
                    e = ex2_(accP0[3] * TWOGL2E); zpd1 += e; tz1 = fmaf(e, zb1, tz1);
                    e = ex2_(accP1[2] * TWOGL2E); zpd1 += e; tz1 = fmaf(e, zb2, tz1);
                    e = ex2_(accP1[3] * TWOGL2E); zpd1 += e; tz1 = fmaf(e, zb3, tz1);
                }
            }
        }

        if (t + 1 < T_TILES) CPA_WAIT0();
        __syncthreads();
    }

    /* reduce quad lanes */
#pragma unroll
    for (int o = 1; o <= 2; o <<= 1) {
        zfd0 += __shfl_xor_sync(0xffffffffu, zfd0, o);
        zpd0 += __shfl_xor_sync(0xffffffffu, zpd0, o);
        tz0  += __shfl_xor_sync(0xffffffffu, tz0, o);
        zfd1 += __shfl_xor_sync(0xffffffffu, zfd1, o);
        zpd1 += __shfl_xor_sync(0xffffffffu, zpd1, o);
        tz1  += __shfl_xor_sync(0xffffffffu, tz1, o);
    }
    /* combine the two column halves via smem */
    float* red = (float*)(sm + OFF_RED);
    if (ch == 1 && q == 0) {
        red[r0] = zfd0;          red[r0 + 8] = zfd1;
        red[64 + r0] = zpd0;     red[64 + r0 + 8] = zpd1;
        red[128 + r0] = tz0;     red[128 + r0 + 8] = tz1;
    }
    __syncthreads();
    float val = 0.f;
    if (ch == 0 && q == 0) {
        const float ZF0 = zfd0 + red[r0];
        const float ZF1 = zfd1 + red[r0 + 8];
        const float ZP0 = zpd0 + red[64 + r0];
        const float ZP1 = zpd1 + red[64 + r0 + 8];
        const float TZ0 = tz0 + red[128 + r0];
        const float TZ1 = tz1 + red[128 + r0 + 8];
        const int na = b * NN + n0, nb_ = na + 8;
        /* ce = ln(ZF') - ln2 * TZ'/ZP  (n1 cancels exactly) */
        const float ce0 = logf(ZF0) - LN2 * (TZ0 / ZP0);
        const float ce1 = logf(ZF1) - LN2 * (TZ1 / ZP1);
        val = w[na] * ce0 + w[nb_] * ce1;
    }
#pragma unroll
    for (int o = 16; o >= 4; o >>= 1) val += __shfl_down_sync(0xffffffffu, val, o);
    float* wsum = (float*)(sm + OFF_WSUM);
    if (lane == 0) wsum[wid] = val;
    __syncthreads();
    if (tid < 4) {
        float v = wsum[tid];
        v += __shfl_down_sync(0xfu, v, 2);
        v += __shfl_down_sync(0xfu, v, 1);
        if (tid == 0) g_cep[b * 64 + bx] = v;
    }

    /* ---- ticket: last CTA writes all 8 outputs ---- */
    __shared__ unsigned int lastTicket;
    __threadfence();
    if (tid == 0) lastTicket = atomicAdd(&g_ctr, 1u);
    __syncthreads();
    if (lastTicket == NCTA - 1) {
        __threadfence();
        float v = g_cep[tid];
#pragma unroll
        for (int o = 16; o > 0; o >>= 1) v += __shfl_down_sync(0xffffffffu, v, o);
        if (lane == 0) wsum[wid] = v;
        __syncthreads();
        if (tid < 4) out[tid] = wsum[2 * tid] + wsum[2 * tid + 1];
        if (tid >= 32 && tid < 96) {
            const int i = tid - 32;
            float r = g_regp[i];
#pragma unroll
            for (int o = 8; o > 0; o >>= 1) r += __shfl_down_sync(0xffffffffu, r, o, 16);
            if ((i & 15) == 0) out[4 + (i >> 4)] = r * (1.0f / (float)(NN * DD));
        }
        if (tid == 0) g_ctr = 0;
    }
}

/* -------------------------------- launcher ------------------------------- */
extern "C" void kernel_launch(void* const* d_in, const int* in_sizes, int n_in,
                              void* d_out, int out_size)
{
    const float* points = (const float*)d_in[0];
    const float* f1     = (const float*)d_in[1];
    const float* f2     = (const float*)d_in[2];
    const float* w      = (const float*)d_in[3];
    float* out          = (float*)d_out;

    static bool attr_set = false;
    if (!attr_set) {
        cudaFuncSetAttribute(ce_kernel, cudaFuncAttributeMaxDynamicSharedMemorySize, SMEM_CE);
        attr_set = true;
    }

    prep_kernel<<<BB * NN / 256, 256>>>(points, f1, f2);
    ce_kernel<<<dim3(NN / ROWS, BB), THREADS, SMEM_CE>>>(w, out);
}